// round 5
// baseline (speedup 1.0000x reference)
#include <cuda_runtime.h>
#include <math.h>

#define T_TOK 2048
#define NE 8
#define TOPK 2
#define HD 2048
#define ID 1408
#define ISD 5632

#define BM 128
#define BN 64
#define BK 16
#define NSTAGE 3
#define SSTR 20   // smem row stride in floats (16 + 4 pad)

#define SWIGLU_SMEM (NSTAGE * (BM + BN + BN) * SSTR * sizeof(float))  // 61440
#define DOWN_SMEM   (NSTAGE * (BM + BN) * SSTR * sizeof(float))       // 46080

// ---------------- scratch (static device globals; no allocation) -------------
__device__ float d_Hs[(size_t)T_TOK * ISD];
__device__ float d_Hr[(size_t)NE * T_TOK * ID];
__device__ float d_Y [(size_t)NE * T_TOK * HD];
__device__ int   d_tok[NE * T_TOK];
__device__ float d_wt [NE * T_TOK];
__device__ int   d_cnt[NE];
__device__ int   d_slot[T_TOK * TOPK];
__device__ int   d_topki[T_TOK * TOPK];
__device__ float d_topkw[T_TOK * TOPK];

// ---------------- small PTX helpers ------------------------------------------
__device__ __forceinline__ unsigned smem_u32(const void* p) {
    return (unsigned)__cvta_generic_to_shared(p);
}
__device__ __forceinline__ void cp16(unsigned dst, const void* src) {
    asm volatile("cp.async.cg.shared.global [%0], [%1], 16;\n" :: "r"(dst), "l"(src));
}
__device__ __forceinline__ void cp_commit() { asm volatile("cp.async.commit_group;\n"); }
template <int N>
__device__ __forceinline__ void cp_wait() { asm volatile("cp.async.wait_group %0;\n" :: "n"(N)); }
__device__ __forceinline__ unsigned f2tf(float f) {
    unsigned r; asm("cvt.rna.tf32.f32 %0, %1;" : "=r"(r) : "f"(f)); return r;
}
__device__ __forceinline__ void mma1688(float c[4], const unsigned a[4], const unsigned b[2]) {
    asm volatile(
        "mma.sync.aligned.m16n8k8.row.col.f32.tf32.tf32.f32 "
        "{%0,%1,%2,%3},{%4,%5,%6,%7},{%8,%9},{%0,%1,%2,%3};\n"
        : "+f"(c[0]), "+f"(c[1]), "+f"(c[2]), "+f"(c[3])
        : "r"(a[0]), "r"(a[1]), "r"(a[2]), "r"(a[3]), "r"(b[0]), "r"(b[1]));
}

// ---------------- routing ----------------------------------------------------
__global__ void route_kernel(const float* __restrict__ x, const float* __restrict__ gw)
{
    int warp = (blockIdx.x * blockDim.x + threadIdx.x) >> 5;
    int lane = threadIdx.x & 31;
    if (warp >= T_TOK) return;
    const float* xr = x + (size_t)warp * HD;

    float s[NE];
#pragma unroll
    for (int e = 0; e < NE; e++) s[e] = 0.f;
    for (int k = lane; k < HD; k += 32) {
        float xv = xr[k];
#pragma unroll
        for (int e = 0; e < NE; e++) s[e] += xv * gw[e * HD + k];
    }
#pragma unroll
    for (int e = 0; e < NE; e++)
#pragma unroll
        for (int off = 16; off; off >>= 1)
            s[e] += __shfl_down_sync(0xffffffffu, s[e], off);

    if (lane == 0) {
        float mx = s[0];
#pragma unroll
        for (int e = 1; e < NE; e++) mx = fmaxf(mx, s[e]);
        float g[NE], sum = 0.f;
#pragma unroll
        for (int e = 0; e < NE; e++) { g[e] = expf(s[e] - mx); sum += g[e]; }
        float inv = 1.f / sum;
#pragma unroll
        for (int e = 0; e < NE; e++) g[e] *= inv;
        int i0 = 0; float v0 = g[0];
#pragma unroll
        for (int e = 1; e < NE; e++) if (g[e] > v0) { v0 = g[e]; i0 = e; }
        int i1 = -1; float v1 = -1.f;
#pragma unroll
        for (int e = 0; e < NE; e++) if (e != i0 && g[e] > v1) { v1 = g[e]; i1 = e; }
        float dn = 1.f / (v0 + v1);
        d_topki[warp * 2 + 0] = i0;  d_topkw[warp * 2 + 0] = v0 * dn;
        d_topki[warp * 2 + 1] = i1;  d_topkw[warp * 2 + 1] = v1 * dn;
    }
}

// ---------------- deterministic per-expert compaction -------------------------
__global__ void build_kernel()
{
    int e = blockIdx.x;
    int tid = threadIdx.x;
    int lane = tid & 31, w = tid >> 5;
    __shared__ int warp_sums[8];
    __shared__ int s_base;
    if (tid == 0) s_base = 0;
    __syncthreads();

    for (int c = 0; c < T_TOK; c += 256) {
        int t = c + tid;
        int k = -1;
        if (d_topki[2 * t] == e) k = 0;
        else if (d_topki[2 * t + 1] == e) k = 1;
        int flag = (k >= 0) ? 1 : 0;
        unsigned bal = __ballot_sync(0xffffffffu, flag);
        int pre = __popc(bal & ((1u << lane) - 1u));
        if (lane == 31) warp_sums[w] = pre + flag;
        __syncthreads();
        int wbase = 0;
        for (int i = 0; i < w; i++) wbase += warp_sums[i];
        int pos = s_base + wbase + pre;
        if (flag) {
            d_tok [e * T_TOK + pos] = t;
            d_wt  [e * T_TOK + pos] = d_topkw[2 * t + k];
            d_slot[2 * t + k]       = e * T_TOK + pos;
        }
        __syncthreads();
        if (tid == 0) {
            int tot = 0;
            for (int i = 0; i < 8; i++) tot += warp_sums[i];
            s_base += tot;
        }
        __syncthreads();
    }
    if (tid == 0) d_cnt[e] = s_base;
}

// ================= TF32 MMA fused gate+up with SiLU epilogue ==================
// 3-stage cp.async pipeline, single __syncthreads per K-iteration, dynamic smem.
template <bool EXPERT>
__global__ __launch_bounds__(256, 1)
void swiglu_mma_k(const float* __restrict__ A,
                  const float* __restrict__ Bg_all,
                  const float* __restrict__ Bu_all,
                  int N, int Kd)
{
    extern __shared__ float smem[];
    float* As_  = smem;                               // NSTAGE*BM*SSTR
    float* Bgs_ = As_  + NSTAGE * BM * SSTR;          // NSTAGE*BN*SSTR
    float* Bus_ = Bgs_ + NSTAGE * BN * SSTR;          // NSTAGE*BN*SSTR

    const int z = EXPERT ? blockIdx.z : 0;
    const float* Bg = Bg_all + (size_t)z * N * Kd;
    const float* Bu = Bu_all + (size_t)z * N * Kd;
    float* C = EXPERT ? (d_Hr + (size_t)z * T_TOK * N) : d_Hs;
    const int M = EXPERT ? d_cnt[z] : T_TOK;

    const int row0 = blockIdx.y * BM;
    if (row0 >= M) return;
    const int col0 = blockIdx.x * BN;

    const int tid = threadIdx.x, lane = tid & 31, warp = tid >> 5;
    const int wm = warp >> 1, wn = warp & 1;
    const int gr = lane >> 2, gc = lane & 3;

    const int ar1 = tid >> 2, ar2 = 64 + (tid >> 2);
    const int kc  = (tid & 3) * 4;
    int r1 = row0 + ar1, r2 = row0 + ar2;
    int g1 = (r1 < M) ? (EXPERT ? d_tok[z * T_TOK + r1] : r1) : 0;
    int g2 = (r2 < M) ? (EXPERT ? d_tok[z * T_TOK + r2] : r2) : 0;
    const float* Ap1 = A + (size_t)g1 * Kd + kc;
    const float* Ap2 = A + (size_t)g2 * Kd + kc;
    const int br = tid >> 2;
    const float* Bgp = Bg + (size_t)(col0 + br) * Kd + kc;
    const float* Bup = Bu + (size_t)(col0 + br) * Kd + kc;

    unsigned sa1[NSTAGE], sa2[NSTAGE], sbg[NSTAGE], sbu[NSTAGE];
#pragma unroll
    for (int s = 0; s < NSTAGE; s++) {
        sa1[s] = smem_u32(&As_ [s * BM * SSTR + ar1 * SSTR + kc]);
        sa2[s] = smem_u32(&As_ [s * BM * SSTR + ar2 * SSTR + kc]);
        sbg[s] = smem_u32(&Bgs_[s * BN * SSTR + br  * SSTR + kc]);
        sbu[s] = smem_u32(&Bus_[s * BN * SSTR + br  * SSTR + kc]);
    }

    float accg[2][4][4] = {}, accu[2][4][4] = {};

    const int Kt = Kd / BK;
    // prologue: prefetch stages 0 and 1
#pragma unroll
    for (int p = 0; p < 2; p++) {
        const int ko = p * BK;
        cp16(sa1[p], Ap1 + ko); cp16(sa2[p], Ap2 + ko);
        cp16(sbg[p], Bgp + ko); cp16(sbu[p], Bup + ko);
        cp_commit();
    }

    for (int kt = 0; kt < Kt; kt++) {
        const int cur = kt % NSTAGE;
        cp_wait<1>();          // tile kt landed
        __syncthreads();       // all warps past tile kt-1 -> stage (kt+2)%3 free

        if (kt + 2 < Kt) {
            const int nst = (kt + 2) % NSTAGE;
            const int ko = (kt + 2) * BK;
            cp16(sa1[nst], Ap1 + ko); cp16(sa2[nst], Ap2 + ko);
            cp16(sbg[nst], Bgp + ko); cp16(sbu[nst], Bup + ko);
        }
        cp_commit();           // empty group near the tail keeps the count uniform

        const float* as  = As_  + cur * BM * SSTR;
        const float* bgs = Bgs_ + cur * BN * SSTR;
        const float* bus = Bus_ + cur * BN * SSTR;
#pragma unroll
        for (int ks = 0; ks < 2; ks++) {
            const int k = ks * 8;
            unsigned afr[2][4];
#pragma unroll
            for (int mt = 0; mt < 2; mt++) {
                const int mb = wm * 32 + mt * 16;
                afr[mt][0] = f2tf(as[(mb + gr    ) * SSTR + k + gc    ]);
                afr[mt][1] = f2tf(as[(mb + gr + 8) * SSTR + k + gc    ]);
                afr[mt][2] = f2tf(as[(mb + gr    ) * SSTR + k + gc + 4]);
                afr[mt][3] = f2tf(as[(mb + gr + 8) * SSTR + k + gc + 4]);
            }
#pragma unroll
            for (int nt = 0; nt < 4; nt++) {
                const int nb = wn * 32 + nt * 8;
                unsigned bg[2], bu[2];
                bg[0] = f2tf(bgs[(nb + gr) * SSTR + k + gc    ]);
                bg[1] = f2tf(bgs[(nb + gr) * SSTR + k + gc + 4]);
                bu[0] = f2tf(bus[(nb + gr) * SSTR + k + gc    ]);
                bu[1] = f2tf(bus[(nb + gr) * SSTR + k + gc + 4]);
#pragma unroll
                for (int mt = 0; mt < 2; mt++) {
                    mma1688(accg[mt][nt], afr[mt], bg);
                    mma1688(accu[mt][nt], afr[mt], bu);
                }
            }
        }
    }

    // epilogue: silu(g)*u
#pragma unroll
    for (int mt = 0; mt < 2; mt++) {
        const int mlo = row0 + wm * 32 + mt * 16 + gr;
        const int mhi = mlo + 8;
#pragma unroll
        for (int nt = 0; nt < 4; nt++) {
            const int n = col0 + wn * 32 + nt * 8 + gc * 2;
            if (mlo < M) {
                float g0 = accg[mt][nt][0], g1v = accg[mt][nt][1];
                float2 v;
                v.x = g0  / (1.f + expf(-g0 )) * accu[mt][nt][0];
                v.y = g1v / (1.f + expf(-g1v)) * accu[mt][nt][1];
                *(float2*)(C + (size_t)mlo * N + n) = v;
            }
            if (mhi < M) {
                float g2 = accg[mt][nt][2], g3 = accg[mt][nt][3];
                float2 v;
                v.x = g2 / (1.f + expf(-g2)) * accu[mt][nt][2];
                v.y = g3 / (1.f + expf(-g3)) * accu[mt][nt][3];
                *(float2*)(C + (size_t)mhi * N + n) = v;
            }
        }
    }
}

// ================= TF32 MMA down-projection ===================================
template <bool EXPERT>
__global__ __launch_bounds__(256, 1)
void down_mma_k(const float* __restrict__ B_all, float* __restrict__ Cout,
                int N, int Kd)
{
    extern __shared__ float smem[];
    float* As_ = smem;                         // NSTAGE*BM*SSTR
    float* Bs_ = As_ + NSTAGE * BM * SSTR;     // NSTAGE*BN*SSTR

    const int z = EXPERT ? blockIdx.z : 0;
    const float* A = EXPERT ? (d_Hr + (size_t)z * T_TOK * Kd) : d_Hs;
    const float* B = B_all + (size_t)z * N * Kd;
    float* C = EXPERT ? (d_Y + (size_t)z * T_TOK * N) : Cout;
    const int M = EXPERT ? d_cnt[z] : T_TOK;

    const int row0 = blockIdx.y * BM;
    if (row0 >= M) return;
    const int col0 = blockIdx.x * BN;

    const int tid = threadIdx.x, lane = tid & 31, warp = tid >> 5;
    const int wm = warp >> 1, wn = warp & 1;
    const int gr = lane >> 2, gc = lane & 3;

    const int ar1 = tid >> 2, ar2 = 64 + (tid >> 2);
    const int kc  = (tid & 3) * 4;
    int r1 = row0 + ar1, r2 = row0 + ar2;
    const float* Ap1 = A + (size_t)((r1 < M) ? r1 : 0) * Kd + kc;
    const float* Ap2 = A + (size_t)((r2 < M) ? r2 : 0) * Kd + kc;
    const int br = tid >> 2;
    const float* Bp = B + (size_t)(col0 + br) * Kd + kc;

    unsigned sa1[NSTAGE], sa2[NSTAGE], sb[NSTAGE];
#pragma unroll
    for (int s = 0; s < NSTAGE; s++) {
        sa1[s] = smem_u32(&As_[s * BM * SSTR + ar1 * SSTR + kc]);
        sa2[s] = smem_u32(&As_[s * BM * SSTR + ar2 * SSTR + kc]);
        sb [s] = smem_u32(&Bs_[s * BN * SSTR + br  * SSTR + kc]);
    }

    float acc[2][4][4] = {};

    const int Kt = Kd / BK;
#pragma unroll
    for (int p = 0; p < 2; p++) {
        const int ko = p * BK;
        cp16(sa1[p], Ap1 + ko); cp16(sa2[p], Ap2 + ko); cp16(sb[p], Bp + ko);
        cp_commit();
    }

    for (int kt = 0; kt < Kt; kt++) {
        const int cur = kt % NSTAGE;
        cp_wait<1>();
        __syncthreads();

        if (kt + 2 < Kt) {
            const int nst = (kt + 2) % NSTAGE;
            const int ko = (kt + 2) * BK;
            cp16(sa1[nst], Ap1 + ko); cp16(sa2[nst], Ap2 + ko); cp16(sb[nst], Bp + ko);
        }
        cp_commit();

        const float* as = As_ + cur * BM * SSTR;
        const float* bs = Bs_ + cur * BN * SSTR;
#pragma unroll
        for (int ks = 0; ks < 2; ks++) {
            const int k = ks * 8;
            unsigned afr[2][4];
#pragma unroll
            for (int mt = 0; mt < 2; mt++) {
                const int mb = wm * 32 + mt * 16;
                afr[mt][0] = f2tf(as[(mb + gr    ) * SSTR + k + gc    ]);
                afr[mt][1] = f2tf(as[(mb + gr + 8) * SSTR + k + gc    ]);
                afr[mt][2] = f2tf(as[(mb + gr    ) * SSTR + k + gc + 4]);
                afr[mt][3] = f2tf(as[(mb + gr + 8) * SSTR + k + gc + 4]);
            }
#pragma unroll
            for (int nt = 0; nt < 4; nt++) {
                const int nb = wn * 32 + nt * 8;
                unsigned bf[2];
                bf[0] = f2tf(bs[(nb + gr) * SSTR + k + gc    ]);
                bf[1] = f2tf(bs[(nb + gr) * SSTR + k + gc + 4]);
#pragma unroll
                for (int mt = 0; mt < 2; mt++)
                    mma1688(acc[mt][nt], afr[mt], bf);
            }
        }
    }

#pragma unroll
    for (int mt = 0; mt < 2; mt++) {
        const int mlo = row0 + wm * 32 + mt * 16 + gr;
        const int mhi = mlo + 8;
        float slo = 1.f, shi = 1.f;
        if (EXPERT) {
            if (mlo < M) slo = d_wt[z * T_TOK + mlo];
            if (mhi < M) shi = d_wt[z * T_TOK + mhi];
        }
#pragma unroll
        for (int nt = 0; nt < 4; nt++) {
            const int n = col0 + wn * 32 + nt * 8 + gc * 2;
            if (mlo < M)
                *(float2*)(C + (size_t)mlo * N + n) =
                    make_float2(acc[mt][nt][0] * slo, acc[mt][nt][1] * slo);
            if (mhi < M)
                *(float2*)(C + (size_t)mhi * N + n) =
                    make_float2(acc[mt][nt][2] * shi, acc[mt][nt][3] * shi);
        }
    }
}

// ---------------- final combine ----------------------------------------------
__global__ void combine_kernel(float* __restrict__ out)
{
    int idx = blockIdx.x * blockDim.x + threadIdx.x;
    int t  = idx / (HD / 4);
    int h4 = idx % (HD / 4);
    int s0 = d_slot[2 * t], s1 = d_slot[2 * t + 1];
    float4 o = ((float4*)out)[idx];
    float4 a = ((const float4*)(d_Y + (size_t)s0 * HD))[h4];
    float4 b = ((const float4*)(d_Y + (size_t)s1 * HD))[h4];
    o.x += a.x + b.x;  o.y += a.y + b.y;  o.z += a.z + b.z;  o.w += a.w + b.w;
    ((float4*)out)[idx] = o;
}

// ---------------- launcher ---------------------------------------------------
extern "C" void kernel_launch(void* const* d_in, const int* in_sizes, int n_in,
                              void* d_out, int out_size)
{
    const float* x   = (const float*)d_in[0];
    const float* gw  = (const float*)d_in[1];
    const float* egw = (const float*)d_in[2];
    const float* euw = (const float*)d_in[3];
    const float* edw = (const float*)d_in[4];
    const float* sgw = (const float*)d_in[5];
    const float* suw = (const float*)d_in[6];
    const float* sdw = (const float*)d_in[7];
    float* out = (float*)d_out;

    // opt-in for >48KB dynamic smem (host attribute calls; idempotent,
    // not stream ops -> legal under graph capture)
    cudaFuncSetAttribute(swiglu_mma_k<false>, cudaFuncAttributeMaxDynamicSharedMemorySize, (int)SWIGLU_SMEM);
    cudaFuncSetAttribute(swiglu_mma_k<true >, cudaFuncAttributeMaxDynamicSharedMemorySize, (int)SWIGLU_SMEM);
    cudaFuncSetAttribute(down_mma_k<false>,   cudaFuncAttributeMaxDynamicSharedMemorySize, (int)DOWN_SMEM);
    cudaFuncSetAttribute(down_mma_k<true >,   cudaFuncAttributeMaxDynamicSharedMemorySize, (int)DOWN_SMEM);

    route_kernel<<<T_TOK * 32 / 256, 256>>>(x, gw);
    build_kernel<<<NE, 256>>>();
    swiglu_mma_k<false><<<dim3(ISD / BN, T_TOK / BM, 1), 256, SWIGLU_SMEM>>>(x, sgw, suw, ISD, HD);
    swiglu_mma_k<true ><<<dim3(ID  / BN, T_TOK / BM, NE), 256, SWIGLU_SMEM>>>(x, egw, euw, ID, HD);
    down_mma_k<false><<<dim3(HD / BN, T_TOK / BM, 1), 256, DOWN_SMEM>>>(sdw, out, HD, ISD);
    down_mma_k<true ><<<dim3(HD / BN, T_TOK / BM, NE), 256, DOWN_SMEM>>>(edw, nullptr, HD, ID);
    combine_kernel<<<(T_TOK * HD / 4) / 256, 256>>>(out);
}